// round 10
// baseline (speedup 1.0000x reference)
#include <cuda_runtime.h>
#include <cuda_fp16.h>
#include <cstdint>

#define Bsz   8
#define CI    512
#define CO    512
#define HW    1024
#define NTAP  9
#define ASCALE 1024.0f

__device__ __half g_Ah[(size_t)NTAP * CO * CI];        // [tap][o][i] = w*gain*1024
__device__ __half g_Bh[(size_t)Bsz * HW * CI];         // [b][n][i]   = x*(s+1)
__device__ __half g_yh[(size_t)Bsz * NTAP * CO * HW];  // 75.5 MB (scaled by 1024)
__device__ float  g_demod[Bsz * CO];

__device__ __forceinline__ uint32_t smaddr(const void* p) {
    uint32_t a;
    asm("{ .reg .u64 t; cvta.to.shared.u64 t, %1; cvt.u32.u64 %0, t; }" : "=r"(a) : "l"(p));
    return a;
}
__device__ __forceinline__ void cp16(uint32_t dst, const void* src) {
    asm volatile("cp.async.cg.shared.global [%0], [%1], 16;" :: "r"(dst), "l"(src));
}
__device__ __forceinline__ void cp_commit() { asm volatile("cp.async.commit_group;"); }
template<int N> __device__ __forceinline__ void cp_wait() {
    asm volatile("cp.async.wait_group %0;" :: "n"(N));
}
__device__ __forceinline__ void ldsm4(uint32_t& r0, uint32_t& r1, uint32_t& r2,
                                      uint32_t& r3, uint32_t addr) {
    asm volatile("ldmatrix.sync.aligned.m8n8.x4.shared.b16 {%0,%1,%2,%3}, [%4];"
                 : "=r"(r0), "=r"(r1), "=r"(r2), "=r"(r3) : "r"(addr));
}

// ---------------- prep W + demod: grid 512, block 256 ----------------
__global__ void __launch_bounds__(256) prep_w_kernel(const float* __restrict__ w,
                                                     const float* __restrict__ styles) {
    const int o = blockIdx.x, tid = threadIdx.x, wid = tid >> 5, lane = tid & 31;
    const float gain = 1.0f / 1536.0f;
    __shared__ float sW2[CI];
    const float* wo = w + (size_t)o * CI * NTAP;

    for (int i = tid; i < CI; i += 256) {
        float acc = 0.f;
        #pragma unroll
        for (int t = 0; t < 9; t++) {
            float v = wo[i * 9 + t] * gain;
            acc += v * v;
            g_Ah[((size_t)t * CO + o) * CI + i] = __float2half_rn(v * ASCALE);
        }
        sW2[i] = acc;
    }
    __syncthreads();
    const int b = wid;
    float sum = 0.f;
    for (int i = lane; i < CI; i += 32) {
        float s = styles[b * CI + i] + 1.0f;
        sum += s * s * sW2[i];
    }
    #pragma unroll
    for (int o2 = 16; o2; o2 >>= 1) sum += __shfl_xor_sync(0xffffffffu, sum, o2);
    if (lane == 0) g_demod[b * CO + o] = rsqrtf(sum + 1e-8f);
}

// ---------------- prep X: B'[b][n][i] transpose, grid (8,8,16) -----------------
__global__ void __launch_bounds__(256) prep_x_kernel(const float* __restrict__ x,
                                                     const float* __restrict__ styles) {
    const int b = blockIdx.x, it = blockIdx.y, nt = blockIdx.z;
    const int i0 = it * 64, n0 = nt * 64;
    __shared__ float sx[64][65];

    #pragma unroll
    for (int e = 0; e < 16; e++) {
        int idx = e * 256 + threadIdx.x;
        int ii = idx >> 6, nn = idx & 63;
        float s = styles[b * CI + i0 + ii] + 1.0f;
        sx[ii][nn] = x[((size_t)b * CI + i0 + ii) * HW + n0 + nn] * s;
    }
    __syncthreads();
    #pragma unroll
    for (int e = 0; e < 16; e++) {
        int idx = e * 256 + threadIdx.x;
        int nn = idx >> 6, ii = idx & 63;
        g_Bh[((size_t)b * HW + n0 + nn) * CI + i0 + ii] = __float2half_rn(sx[ii][nn]);
    }
}

// ---------------- GEMM: 256x128x32 tile, warp 64x64, 4-stage, LDSM -------------
#define SROW 80
#define AREG (256 * SROW)          // 20480 B
#define BREG (128 * SROW)          // 10240 B
#define STGB (AREG + BREG)         // 30720 B per stage
#define CROW 136                   // epilogue smem stride (halfs); 272B rows, 16B-aligned
#define GEMM_SMEM (4 * STGB)       // 122880 B (>= 256*CROW*2 = 69632 for epilogue)

__global__ void __launch_bounds__(256, 1) gemm_kernel() {
    extern __shared__ char gsm[];
    const uint32_t sbase = smaddr(gsm);

    const int tid = threadIdx.x, wid = tid >> 5, lane = tid & 31;
    const int lq = lane >> 2, qq = lane & 3;
    const int wm = wid >> 1, wn = wid & 1;        // 4x2 warps, warp tile 64x64
    const int mwarp = wm * 64, nwarp = wn * 64;

    const int n0 = blockIdx.x * 128, m0 = blockIdx.y * 256, gz = blockIdx.z;
    const int b = gz / 9, tap = gz - b * 9;

    const __half* Ag = g_Ah + (size_t)tap * CO * CI;
    const __half* Bg = g_Bh + (size_t)b * HW * CI;
    __half*       Ch = g_yh + (size_t)gz * CO * HW;

    // cp.async: A = 256 rows x 4 chunks (thread t -> row t), B = 128 rows x 4 chunks
    const int b_row = tid & 127;
    const int b_c0  = (tid >> 7) * 2;

    auto load_stage = [&](int s, int kt) {
        const uint32_t st = sbase + (uint32_t)s * STGB;
        const int k0 = kt * 32;
        const __half* ag = Ag + (size_t)(m0 + tid) * CI + k0;
        #pragma unroll
        for (int c = 0; c < 4; c++)
            cp16(st + (uint32_t)tid * SROW + (uint32_t)c * 16, ag + c * 8);
        const __half* bg = Bg + (size_t)(n0 + b_row) * CI + k0;
        #pragma unroll
        for (int j = 0; j < 2; j++) {
            int c = b_c0 + j;
            cp16(st + AREG + (uint32_t)b_row * SROW + (uint32_t)c * 16, bg + c * 8);
        }
        cp_commit();
    };

    load_stage(0, 0); load_stage(1, 1); load_stage(2, 2);

    float c[4][8][4];
    #pragma unroll
    for (int i = 0; i < 4; i++)
        #pragma unroll
        for (int j = 0; j < 8; j++)
            #pragma unroll
            for (int k = 0; k < 4; k++) c[i][j][k] = 0.f;

    const int lrow = lane & 15;
    const int hi   = lane >> 4;

    for (int kt = 0; kt < 16; kt++) {
        cp_wait<2>();
        __syncthreads();
        if (kt + 3 < 16) load_stage((kt + 3) & 3, kt + 3);

        const uint32_t sA = sbase + (uint32_t)(kt & 3) * STGB;
        const uint32_t sB = sA + AREG;

        #pragma unroll
        for (int ks = 0; ks < 2; ks++) {
            const uint32_t coff = (uint32_t)(2 * ks + hi) * 16;
            uint32_t bf[4][4];
            #pragma unroll
            for (int np = 0; np < 4; np++)
                ldsm4(bf[np][0], bf[np][1], bf[np][2], bf[np][3],
                      sB + (uint32_t)(nwarp + np * 16 + lrow) * SROW + coff);
            #pragma unroll
            for (int mt = 0; mt < 4; mt++) {
                uint32_t a0, a1, a2, a3;
                ldsm4(a0, a1, a2, a3,
                      sA + (uint32_t)(mwarp + mt * 16 + lrow) * SROW + coff);
                #pragma unroll
                for (int nt = 0; nt < 8; nt++) {
                    uint32_t b0 = bf[nt >> 1][nt & 1];
                    uint32_t b1 = bf[nt >> 1][2 + (nt & 1)];
                    asm volatile(
                        "mma.sync.aligned.m16n8k16.row.col.f32.f16.f16.f32 "
                        "{%0,%1,%2,%3}, {%4,%5,%6,%7}, {%8,%9}, {%0,%1,%2,%3};"
                        : "+f"(c[mt][nt][0]), "+f"(c[mt][nt][1]),
                          "+f"(c[mt][nt][2]), "+f"(c[mt][nt][3])
                        : "r"(a0), "r"(a1), "r"(a2), "r"(a3), "r"(b0), "r"(b1));
                }
            }
        }
    }

    // epilogue: stage fp16 C in smem, then coalesced float4 stores
    __syncthreads();
    __half* sC = (__half*)gsm;
    #pragma unroll
    for (int mt = 0; mt < 4; mt++)
        #pragma unroll
        for (int nt = 0; nt < 8; nt++) {
            int row = mwarp + mt * 16 + lq;
            int col = nwarp + nt * 8 + 2 * qq;
            *(__half2*)&sC[(size_t)row * CROW + col] =
                __floats2half2_rn(c[mt][nt][0], c[mt][nt][1]);
            *(__half2*)&sC[(size_t)(row + 8) * CROW + col] =
                __floats2half2_rn(c[mt][nt][2], c[mt][nt][3]);
        }
    __syncthreads();
    #pragma unroll
    for (int it = 0; it < 16; it++) {
        int e = it * 256 + tid;          // 4096 chunks = 256 rows x 16 segs
        int row = e >> 4, seg = e & 15;
        uint4 v = *(const uint4*)&sC[(size_t)row * CROW + seg * 8];
        *(uint4*)(Ch + (size_t)(m0 + row) * HW + n0 + seg * 8) = v;
    }
}

// ---------------- FIR + demod: grid 4096, block 512 ----------------
__global__ void __launch_bounds__(512) fir_kernel(float* __restrict__ out) {
    const int bo = blockIdx.x;
    const int b = bo >> 9, o = bo & 511;
    __shared__ float sY[NTAP][34][34];
    const __half* yb = g_yh + ((size_t)b * NTAP * CO + o) * HW;
    const size_t plane = (size_t)CO * HW;
    const float dd = g_demod[b * CO + o] * (1.0f / ASCALE);

    for (int e = threadIdx.x; e < NTAP * 136; e += 512) {
        int tap = e / 136, p = e - tap * 136;
        if      (p < 34)  sY[tap][0][p] = 0.f;
        else if (p < 68)  sY[tap][33][p - 34] = 0.f;
        else if (p < 102) sY[tap][p - 68][0] = 0.f;
        else              sY[tap][p - 102][33] = 0.f;
    }
    for (int e = threadIdx.x; e < 1152; e += 512) {   // 9 taps * 128 chunks of 8 halfs
        int tap = e >> 7, rem = e & 127;
        int h = rem >> 2, q = rem & 3;
        uint4 v = *(const uint4*)(yb + (size_t)tap * plane + h * 32 + q * 8);
        const __half2* hv = reinterpret_cast<const __half2*>(&v);
        float2 f0 = __half22float2(hv[0]);
        float2 f1 = __half22float2(hv[1]);
        float2 f2 = __half22float2(hv[2]);
        float2 f3 = __half22float2(hv[3]);
        float* d = &sY[tap][h + 1][1 + q * 8];
        d[0] = f0.x; d[1] = f0.y; d[2] = f1.x; d[3] = f1.y;
        d[4] = f2.x; d[5] = f2.y; d[6] = f3.x; d[7] = f3.y;
    }
    __syncthreads();

    const float c1t[2][3][3] = {
        { {0.00f, 0.25f, 0.75f}, {0.75f, 0.75f, 0.25f}, {0.25f, 0.00f, 0.00f} },
        { {0.00f, 0.00f, 0.25f}, {0.25f, 0.75f, 0.75f}, {0.75f, 0.25f, 0.00f} }
    };
    float* ob = out + ((size_t)b * CO + o) * 4096;

    #pragma unroll
    for (int j = 0; j < 2; j++) {
        int pos = threadIdx.x + j * 512;
        int P = pos >> 5, Q = pos & 31;
        float a00 = 0.f, a01 = 0.f, a10 = 0.f, a11 = 0.f;
        #pragma unroll
        for (int dh = 0; dh < 3; dh++)
            #pragma unroll
            for (int kh = 0; kh < 3; kh++) {
                const float ch0 = c1t[0][dh][kh], ch1 = c1t[1][dh][kh];
                if (ch0 == 0.f && ch1 == 0.f) continue;
                #pragma unroll
                for (int dw = 0; dw < 3; dw++)
                    #pragma unroll
                    for (int kw = 0; kw < 3; kw++) {
                        const float cw0 = c1t[0][dw][kw], cw1 = c1t[1][dw][kw];
                        if (cw0 == 0.f && cw1 == 0.f) continue;
                        float v = sY[kh * 3 + kw][P + dh][Q + dw];
                        a00 += (ch0 * cw0) * v;  a01 += (ch0 * cw1) * v;
                        a10 += (ch1 * cw0) * v;  a11 += (ch1 * cw1) * v;
                    }
            }
        *(float2*)(ob + (size_t)(2*P)   * 64 + 2*Q) = make_float2(a00 * dd, a01 * dd);
        *(float2*)(ob + (size_t)(2*P+1) * 64 + 2*Q) = make_float2(a10 * dd, a11 * dd);
    }
}

// ---------------- launch ----------------
extern "C" void kernel_launch(void* const* d_in, const int* in_sizes, int n_in,
                              void* d_out, int out_size) {
    const float* x      = (const float*)d_in[0];
    const float* styles = (const float*)d_in[1];
    const float* w      = (const float*)d_in[2];
    float* out = (float*)d_out;
    (void)in_sizes; (void)n_in; (void)out_size;

    cudaFuncSetAttribute(gemm_kernel, cudaFuncAttributeMaxDynamicSharedMemorySize, GEMM_SMEM);

    prep_w_kernel<<<512, 256>>>(w, styles);
    prep_x_kernel<<<dim3(8, 8, 16), 256>>>(x, styles);
    gemm_kernel<<<dim3(8, 2, 72), 256, GEMM_SMEM>>>();
    fir_kernel<<<Bsz * CO, 512>>>(out);
}

// round 11
// speedup vs baseline: 1.0657x; 1.0657x over previous
#include <cuda_runtime.h>
#include <cuda_fp16.h>
#include <cstdint>

#define Bsz   8
#define CI    512
#define CO    512
#define HW    1024
#define NTAP  9
#define ASCALE 1024.0f

__device__ __half g_Ah[(size_t)NTAP * CO * CI];        // [tap][o][i] = w*gain*1024
__device__ __half g_Bh[(size_t)Bsz * HW * CI];         // [b][n][i]   = x*(s+1)
__device__ __half g_yh[(size_t)Bsz * NTAP * CO * HW];  // 75.5 MB (scaled by 1024)
__device__ float  g_demod[Bsz * CO];

__device__ __forceinline__ uint32_t smaddr(const void* p) {
    uint32_t a;
    asm("{ .reg .u64 t; cvta.to.shared.u64 t, %1; cvt.u32.u64 %0, t; }" : "=r"(a) : "l"(p));
    return a;
}
__device__ __forceinline__ void cp16(uint32_t dst, const void* src) {
    asm volatile("cp.async.cg.shared.global [%0], [%1], 16;" :: "r"(dst), "l"(src));
}
__device__ __forceinline__ void cp_commit() { asm volatile("cp.async.commit_group;"); }
template<int N> __device__ __forceinline__ void cp_wait() {
    asm volatile("cp.async.wait_group %0;" :: "n"(N));
}

// ---------------- merged prep: grid 1536 (512 W + 1024 X), block 256 ----------
__global__ void __launch_bounds__(256) prep_kernel(const float* __restrict__ w,
                                                   const float* __restrict__ x,
                                                   const float* __restrict__ styles) {
    const int tid = threadIdx.x;
    if (blockIdx.x < 512) {
        // ---- prep W + demod (one block per o) ----
        const int o = blockIdx.x, wid = tid >> 5, lane = tid & 31;
        const float gain = 1.0f / 1536.0f;
        __shared__ float sW2[CI];
        const float* wo = w + (size_t)o * CI * NTAP;

        for (int i = tid; i < CI; i += 256) {
            float acc = 0.f;
            #pragma unroll
            for (int t = 0; t < 9; t++) {
                float v = wo[i * 9 + t] * gain;
                acc += v * v;
                g_Ah[((size_t)t * CO + o) * CI + i] = __float2half_rn(v * ASCALE);
            }
            sW2[i] = acc;
        }
        __syncthreads();
        const int b = wid;                  // 8 warps = 8 batches
        float sum = 0.f;
        for (int i = lane; i < CI; i += 32) {
            float s = styles[b * CI + i] + 1.0f;
            sum += s * s * sW2[i];
        }
        #pragma unroll
        for (int o2 = 16; o2; o2 >>= 1) sum += __shfl_xor_sync(0xffffffffu, sum, o2);
        if (lane == 0) g_demod[b * CO + o] = rsqrtf(sum + 1e-8f);
    } else {
        // ---- prep X: B'[b][n][i] = x[b][i][n]*(s+1), 64x64 tile transpose ----
        const int e = blockIdx.x - 512;     // 0..1023
        const int b = e >> 7, it = (e >> 4) & 7, nt = e & 15;
        const int i0 = it * 64, n0 = nt * 64;
        __shared__ float sx[64][65];

        #pragma unroll
        for (int q = 0; q < 16; q++) {
            int idx = q * 256 + tid;
            int ii = idx >> 6, nn = idx & 63;
            float s = styles[b * CI + i0 + ii] + 1.0f;
            sx[ii][nn] = x[((size_t)b * CI + i0 + ii) * HW + n0 + nn] * s;
        }
        __syncthreads();
        #pragma unroll
        for (int q = 0; q < 16; q++) {
            int idx = q * 256 + tid;
            int nn = idx >> 6, ii = idx & 63;
            g_Bh[((size_t)b * HW + n0 + nn) * CI + i0 + ii] = __float2half_rn(sx[ii][nn]);
        }
    }
}

// ---------------- GEMM (R6 verbatim — best measured): fp16 m16n8k16 ------------
#define SA 24
#define STG (128 * SA)

__global__ void __launch_bounds__(256, 2) gemm_kernel() {
    __shared__ __half sm[4][2][STG];   // 48 KB exactly

    const int tid = threadIdx.x, wid = tid >> 5, lane = tid & 31;
    const int lq = lane >> 2, qq = lane & 3;
    const int wm = wid >> 2, wn = wid & 3;       // 2x4 warps, warp tile 64x32
    const int mwarp = wm * 64, nwarp = wn * 32;

    const int n0 = blockIdx.x * 128, m0 = blockIdx.y * 128, gz = blockIdx.z;
    const int b = gz / 9, tap = gz - b * 9;

    const __half* Ag = g_Ah + (size_t)tap * CO * CI;
    const __half* Bg = g_Bh + (size_t)b * HW * CI;
    __half*       Ch = g_yh + (size_t)gz * CO * HW;

    const int l_r = tid >> 1, l_h = tid & 1;

    auto load_stage = [&](int s, int kt) {
        const int k0 = kt * 16;
        cp16(smaddr(&sm[s][0][l_r * SA + l_h * 8]),
             Ag + (size_t)(m0 + l_r) * CI + k0 + l_h * 8);
        cp16(smaddr(&sm[s][1][l_r * SA + l_h * 8]),
             Bg + (size_t)(n0 + l_r) * CI + k0 + l_h * 8);
        cp_commit();
    };

    load_stage(0, 0); load_stage(1, 1); load_stage(2, 2);

    float c[4][4][4];
    #pragma unroll
    for (int i = 0; i < 4; i++)
        #pragma unroll
        for (int j = 0; j < 4; j++)
            #pragma unroll
            for (int k = 0; k < 4; k++) c[i][j][k] = 0.f;

    for (int kt = 0; kt < 32; kt++) {
        cp_wait<2>();
        __syncthreads();
        const __half* As = sm[kt & 3][0];
        const __half* Bs = sm[kt & 3][1];

        if (kt + 3 < 32) load_stage((kt + 3) & 3, kt + 3);

        uint32_t a[4][4], bb[4][2];
        #pragma unroll
        for (int mt = 0; mt < 4; mt++) {
            const __half* ap = &As[(mwarp + mt * 16 + lq) * SA + 2 * qq];
            a[mt][0] = *(const uint32_t*)(ap);
            a[mt][1] = *(const uint32_t*)(ap + 8 * SA);
            a[mt][2] = *(const uint32_t*)(ap + 8);
            a[mt][3] = *(const uint32_t*)(ap + 8 * SA + 8);
        }
        #pragma unroll
        for (int nt = 0; nt < 4; nt++) {
            const __half* bp = &Bs[(nwarp + nt * 8 + lq) * SA + 2 * qq];
            bb[nt][0] = *(const uint32_t*)(bp);
            bb[nt][1] = *(const uint32_t*)(bp + 8);
        }
        #pragma unroll
        for (int mt = 0; mt < 4; mt++)
            #pragma unroll
            for (int nt = 0; nt < 4; nt++)
                asm volatile(
                    "mma.sync.aligned.m16n8k16.row.col.f32.f16.f16.f32 "
                    "{%0,%1,%2,%3}, {%4,%5,%6,%7}, {%8,%9}, {%0,%1,%2,%3};"
                    : "+f"(c[mt][nt][0]), "+f"(c[mt][nt][1]),
                      "+f"(c[mt][nt][2]), "+f"(c[mt][nt][3])
                    : "r"(a[mt][0]), "r"(a[mt][1]), "r"(a[mt][2]), "r"(a[mt][3]),
                      "r"(bb[nt][0]), "r"(bb[nt][1]));
        __syncthreads();
    }

    #pragma unroll
    for (int mt = 0; mt < 4; mt++)
        #pragma unroll
        for (int nt = 0; nt < 4; nt++) {
            int row = m0 + mwarp + mt * 16 + lq;
            int col = n0 + nwarp + nt * 8 + 2 * qq;
            *(__half2*)(Ch + (size_t)row * HW + col) =
                __floats2half2_rn(c[mt][nt][0], c[mt][nt][1]);
            *(__half2*)(Ch + (size_t)(row + 8) * HW + col) =
                __floats2half2_rn(c[mt][nt][2], c[mt][nt][3]);
        }
}

// ---------------- FIR + demod: separable, grid 4096, block 512, dyn smem -------
// sY[9][34][34] (10404 f) + U[34][3][2][32] (6528 f) = 67728 B
#define FIR_SMEM ((10404 + 6528) * 4)

__global__ void __launch_bounds__(512) fir_kernel(float* __restrict__ out) {
    extern __shared__ float fsm[];
    float* sY = fsm;                 // [tap][34][34] flat: tap*1156 + r*34 + c
    float* U  = fsm + 10404;         // [R][kh][ew][32]:   R*192 + kh*64 + ew*32 + Q

    const int bo = blockIdx.x;
    const int b = bo >> 9, o = bo & 511;
    const int tid = threadIdx.x;
    const __half* yb = g_yh + ((size_t)b * NTAP * CO + o) * HW;
    const size_t plane = (size_t)CO * HW;
    const float dd = g_demod[b * CO + o] * (1.0f / ASCALE);

    // halo frame zero
    for (int e = tid; e < NTAP * 136; e += 512) {
        int tap = e / 136, p = e - tap * 136;
        int off;
        if      (p < 34)  off = p;                       // row 0
        else if (p < 68)  off = 33 * 34 + (p - 34);      // row 33
        else if (p < 102) off = (p - 68) * 34;           // col 0
        else              off = (p - 102) * 34 + 33;     // col 33
        sY[tap * 1156 + off] = 0.f;
    }
    // interior fill: 9 taps * 128 chunks of 8 halfs
    for (int e = tid; e < 1152; e += 512) {
        int tap = e >> 7, rem = e & 127;
        int h = rem >> 2, q = rem & 3;
        uint4 v = *(const uint4*)(yb + (size_t)tap * plane + h * 32 + q * 8);
        const __half2* hv = reinterpret_cast<const __half2*>(&v);
        float2 f0 = __half22float2(hv[0]);
        float2 f1 = __half22float2(hv[1]);
        float2 f2 = __half22float2(hv[2]);
        float2 f3 = __half22float2(hv[3]);
        float* d = &sY[tap * 1156 + (h + 1) * 34 + 1 + q * 8];
        d[0] = f0.x; d[1] = f0.y; d[2] = f1.x; d[3] = f1.y;
        d[4] = f2.x; d[5] = f2.y; d[6] = f3.x; d[7] = f3.y;
    }
    __syncthreads();

    // c1t[e][d][k]
    const float c1t[2][3][3] = {
        { {0.00f, 0.25f, 0.75f}, {0.75f, 0.75f, 0.25f}, {0.25f, 0.00f, 0.00f} },
        { {0.00f, 0.00f, 0.25f}, {0.25f, 0.75f, 0.75f}, {0.75f, 0.25f, 0.00f} }
    };

    // pass 1: U[R][kh][ew][Q] = sum_{dw,kw} c1t[ew][dw][kw] * sY[kh*3+kw][R][Q+dw]
    for (int e = tid; e < 3264; e += 512) {        // 34 * 3 * 32
        int R = e / 96, rem = e - R * 96;
        int kh = rem >> 5, Q = rem & 31;
        const float* yrow = &sY[kh * 3 * 1156 + R * 34 + Q];  // [kw][.][dw] via kw*1156+dw
        float u0 = 0.f, u1 = 0.f;
        #pragma unroll
        for (int dw = 0; dw < 3; dw++)
            #pragma unroll
            for (int kw = 0; kw < 3; kw++) {
                const float w0 = c1t[0][dw][kw], w1 = c1t[1][dw][kw];
                if (w0 == 0.f && w1 == 0.f) continue;
                float v = yrow[kw * 1156 + dw];
                u0 += w0 * v;
                u1 += w1 * v;
            }
        U[R * 192 + kh * 64 + Q]      = u0;
        U[R * 192 + kh * 64 + 32 + Q] = u1;
    }
    __syncthreads();

    // pass 2: y2[2P+eh][2Q+ew] = sum_{dh,kh} c1t[eh][dh][kh] * U[P+dh][kh][ew][Q]
    float* ob = out + ((size_t)b * CO + o) * 4096;
    #pragma unroll
    for (int j = 0; j < 2; j++) {
        int pos = tid + j * 512;
        int P = pos >> 5, Q = pos & 31;
        float a00 = 0.f, a01 = 0.f, a10 = 0.f, a11 = 0.f;
        #pragma unroll
        for (int dh = 0; dh < 3; dh++)
            #pragma unroll
            for (int kh = 0; kh < 3; kh++) {
                const float h0 = c1t[0][dh][kh], h1 = c1t[1][dh][kh];
                if (h0 == 0.f && h1 == 0.f) continue;
                float u0 = U[(P + dh) * 192 + kh * 64 + Q];
                float u1 = U[(P + dh) * 192 + kh * 64 + 32 + Q];
                a00 += h0 * u0;  a01 += h0 * u1;
                a10 += h1 * u0;  a11 += h1 * u1;
            }
        *(float2*)(ob + (size_t)(2*P)   * 64 + 2*Q) = make_float2(a00 * dd, a01 * dd);
        *(float2*)(ob + (size_t)(2*P+1) * 64 + 2*Q) = make_float2(a10 * dd, a11 * dd);
    }
}

// ---------------- launch ----------------
extern "C" void kernel_launch(void* const* d_in, const int* in_sizes, int n_in,
                              void* d_out, int out_size) {
    const float* x      = (const float*)d_in[0];
    const float* styles = (const float*)d_in[1];
    const float* w      = (const float*)d_in[2];
    float* out = (float*)d_out;
    (void)in_sizes; (void)n_in; (void)out_size;

    cudaFuncSetAttribute(fir_kernel, cudaFuncAttributeMaxDynamicSharedMemorySize, FIR_SMEM);

    prep_kernel<<<1536, 256>>>(w, x, styles);
    gemm_kernel<<<dim3(8, 4, 72), 256>>>();
    fir_kernel<<<Bsz * CO, 512, FIR_SMEM>>>(out);
}